// round 12
// baseline (speedup 1.0000x reference)
#include <cuda_runtime.h>
#include <cuda_bf16.h>
#include <math.h>
#include <stdint.h>

#define BATCH 16
#define C 256
#define CQK 32
#define NT 256   /* 16x16 */
#define NS 1024  /* 32x32 */

// ---------------- scratch (static device memory; allowed) ----------------
__device__ float g_q_t[BATCH*NT*CQK];
__device__ float g_k_t[BATCH*NT*CQK];
__device__ float g_q_s[BATCH*NS*CQK];
__device__ float g_k_s[BATCH*NS*CQK];
__device__ float g_v_t[BATCH*C*NT];
__device__ float g_v_s[BATCH*C*NS];
__device__ float g_att_t[BATCH*NT*NT];
__device__ float g_att_s[(size_t)BATCH*NS*NS];
__device__ float g_Gt[BATCH*C*C];
__device__ float g_Gs[BATCH*C*C];
__device__ float g_M[BATCH*C*C];
__device__ float g_at[BATCH*C*NT];
__device__ float g_as[BATCH*C*NS];
__device__ float g_off_t[BATCH*27*NT];
__device__ float g_off_s[BATCH*27*NS];
__device__ float g_col_t[(size_t)BATCH*C*9*NT];
__device__ float g_col_s[(size_t)BATCH*C*9*NS];

// ---------------- helpers ----------------
__device__ __forceinline__ uint32_t cvt_pack(float lo, float hi) {
    uint32_t r;
    asm("cvt.rn.bf16x2.f32 %0, %1, %2;" : "=r"(r) : "f"(hi), "f"(lo));
    return r;
}
__device__ __forceinline__ float bfhi_lo(uint32_t p) { return __uint_as_float(p << 16); }
__device__ __forceinline__ float bfhi_hi(uint32_t p) { return __uint_as_float(p & 0xFFFF0000u); }

__device__ __forceinline__ uint32_t smem_u32(const void* p) {
    uint32_t a;
    asm("{ .reg .u64 t; cvta.to.shared.u64 t, %1; cvt.u32.u64 %0, t; }" : "=r"(a) : "l"(p));
    return a;
}

__device__ __forceinline__ void mma_bf16(float* c, const uint32_t* a, const uint32_t* b) {
    asm volatile(
        "mma.sync.aligned.m16n8k16.row.col.f32.bf16.bf16.f32 "
        "{%0,%1,%2,%3}, {%4,%5,%6,%7}, {%8,%9}, {%0,%1,%2,%3};"
        : "+f"(c[0]), "+f"(c[1]), "+f"(c[2]), "+f"(c[3])
        : "r"(a[0]), "r"(a[1]), "r"(a[2]), "r"(a[3]), "r"(b[0]), "r"(b[1]));
}

__device__ __forceinline__ void ldsm_x4(uint32_t* r, uint32_t addr) {
    asm volatile("ldmatrix.sync.aligned.m8n8.x4.shared.b16 {%0,%1,%2,%3}, [%4];"
        : "=r"(r[0]), "=r"(r[1]), "=r"(r[2]), "=r"(r[3]) : "r"(addr));
}

// MUFU-free exp: valid for x <= 0 (softmax post max-subtraction); ~2e-6 rel err.
__device__ __forceinline__ float fast_exp(float x) {
    x = fmaxf(x, -80.f);
    float t = x * 1.4426950408889634f;
    float fi = floorf(t);
    float f = t - fi;
    float p = 1.5252733804059840e-5f;
    p = p * f + 1.5403530393381609e-4f;
    p = p * f + 1.3333558146428443e-3f;
    p = p * f + 9.6181291076284772e-3f;
    p = p * f + 5.5504108664821576e-2f;
    p = p * f + 2.4022650695910071e-1f;
    p = p * f + 6.9314718055994531e-1f;
    p = p * f + 1.0f;
    int n = (int)fi;
    float scale = __int_as_float((n + 127) << 23);
    return p * scale;
}

// ---- split-bf16 tensor GEMM, ldmatrix, templated CTA tile BM x BN x 32 ----
// 8 warps (4m x 2n). Warp tile (BM/4) x (BN/2). BN=128 doubles MMA density per LDSM.
// Smem row-major bf16 tiles, 80-byte pitch, conflict-free LDSM.
template<int BM, int BN, bool BT>
__global__ __launch_bounds__(256, 2)
void gemm_bf16x3(const float* __restrict__ A, const float* __restrict__ B,
                 float* __restrict__ Cc, int M_, int N, int K,
                 long sA, long sB, long sC,
                 const float* __restrict__ bias,
                 const float* __restrict__ residual, int accumulate)
{
    constexpr int MT = BM / 64;            // m16 tiles per warp
    constexpr int NTF = BN / 16;           // n8-tile pairs... B fragments per warp = BN/16
    constexpr int AI = BM / 32;            // A fetch iters
    constexpr int BI = BN / 32;            // B fetch iters
    constexpr int A_SLAB = BM * 80;        // bytes
    constexpr int B_SLAB = BN * 80;        // bytes
    constexpr int B_OFF  = 4 * A_SLAB;     // bytes
    constexpr int APITCH = 20;             // u32
    constexpr int BSH = (BN == 128) ? 7 : 6;

    extern __shared__ uint32_t sm_[];
    uint32_t sb = smem_u32(sm_);

    const float* Ab = A + (long)blockIdx.z*sA;
    const float* Bb = B + (long)blockIdx.z*sB;
    float* Cb = Cc + (long)blockIdx.z*sC;
    const float* Rb = residual ? residual + (long)blockIdx.z*sC : nullptr;

    int tid = threadIdx.x;
    int lane = tid & 31;
    int warp = tid >> 5;
    int wm = warp >> 1;                    // 0..3
    int wn = warp & 1;                     // 0..1
    int row0 = blockIdx.y * BM, col0 = blockIdx.x * BN;

    int q  = lane >> 3, qi = lane & 7;
    int a_dm = (q & 1) * 8 + qi;
    int a_dk = (q >> 1) * 16;
    int b_dn = (q >> 1) * 8 + qi;
    int b_dk = (q & 1) * 16;

    float acc[MT][NTF][4];
    #pragma unroll
    for (int i = 0; i < MT; i++)
        #pragma unroll
        for (int j = 0; j < NTF; j++)
            #pragma unroll
            for (int r = 0; r < 4; r++) acc[i][j][r] = 0.f;

    float4 fa[AI];
    float4 fbt[BT ? BI : 1];
    float  fbn[BT ? 1 : BI][4];

    auto fetchA = [&](int k0) {
        #pragma unroll
        for (int i = 0; i < AI; i++) {
            int slot = tid + i*256;                 // BM*8 = m x 8 k4
            int m = slot >> 3, k4 = slot & 7;
            fa[i] = *(const float4*)&Ab[(long)(row0+m)*K + k0 + k4*4];
        }
    };
    auto storeA = [&](int buf) {
        #pragma unroll
        for (int i = 0; i < AI; i++) {
            int slot = tid + i*256;
            int m = slot >> 3, k4 = slot & 7;
            float x = fa[i].x, y = fa[i].y, z = fa[i].z, w = fa[i].w;
            uint32_t h0 = cvt_pack(x, y), h1 = cvt_pack(z, w);
            uint32_t l0 = cvt_pack(x - bfhi_lo(h0), y - bfhi_hi(h0));
            uint32_t l1 = cvt_pack(z - bfhi_lo(h1), w - bfhi_hi(h1));
            int ih = ((buf*2 + 0)*BM + m)*APITCH + k4*2;
            int il = ((buf*2 + 1)*BM + m)*APITCH + k4*2;
            *(uint2*)&sm_[ih] = make_uint2(h0, h1);
            *(uint2*)&sm_[il] = make_uint2(l0, l1);
        }
    };
    auto fetchB = [&](int k0) {
        if (BT) {
            #pragma unroll
            for (int i = 0; i < BI; i++) {
                int slot = tid + i*256;             // BN*8 = n x 8 k4
                int k4 = slot & 7, n = slot >> 3;
                fbt[i] = *(const float4*)&Bb[(long)(col0+n)*K + k0 + k4*4];
            }
        } else {
            #pragma unroll
            for (int i = 0; i < BI; i++) {
                int slot = tid + i*256;             // 8 kg x BN n
                int n = slot & (BN-1), kg = slot >> BSH;
                #pragma unroll
                for (int j = 0; j < 4; j++)
                    fbn[i][j] = Bb[(long)(k0 + kg*4 + j)*N + col0 + n];
            }
        }
    };
    auto storeB = [&](int buf) {
        #pragma unroll
        for (int i = 0; i < BI; i++) {
            int slot = tid + i*256;
            int n, k4;
            float v0, v1, v2, v3;
            if (BT) {
                n = slot >> 3; k4 = slot & 7;
                v0 = fbt[i].x; v1 = fbt[i].y; v2 = fbt[i].z; v3 = fbt[i].w;
            } else {
                n = slot & (BN-1); k4 = slot >> BSH;
                v0 = fbn[i][0]; v1 = fbn[i][1]; v2 = fbn[i][2]; v3 = fbn[i][3];
            }
            uint32_t h0 = cvt_pack(v0, v1), h1 = cvt_pack(v2, v3);
            uint32_t l0 = cvt_pack(v0 - bfhi_lo(h0), v1 - bfhi_hi(h0));
            uint32_t l1 = cvt_pack(v2 - bfhi_lo(h1), v3 - bfhi_hi(h1));
            int ih = B_OFF/4 + ((buf*2 + 0)*BN + n)*APITCH + k4*2;
            int il = B_OFF/4 + ((buf*2 + 1)*BN + n)*APITCH + k4*2;
            *(uint2*)&sm_[ih] = make_uint2(h0, h1);
            *(uint2*)&sm_[il] = make_uint2(l0, l1);
        }
    };
    auto compute = [&](int buf) {
        uint32_t aHi = sb + (buf*2 + 0)*A_SLAB;
        uint32_t aLo = sb + (buf*2 + 1)*A_SLAB;
        uint32_t bHi = sb + B_OFF + (buf*2 + 0)*B_SLAB;
        uint32_t bLo = sb + B_OFF + (buf*2 + 1)*B_SLAB;
        #pragma unroll
        for (int ks = 0; ks < 2; ks++) {
            uint32_t ah[MT][4], al[MT][4], bh[NTF][2], bl[NTF][2];
            #pragma unroll
            for (int mt = 0; mt < MT; mt++) {
                uint32_t off = (uint32_t)(wm*(MT*16) + mt*16 + a_dm)*80 + ks*32 + a_dk;
                ldsm_x4(ah[mt], aHi + off);
                ldsm_x4(al[mt], aLo + off);
            }
            #pragma unroll
            for (int p = 0; p < NTF/2; p++) {
                uint32_t off = (uint32_t)(wn*(NTF*8) + p*16 + b_dn)*80 + ks*32 + b_dk;
                ldsm_x4(&bh[p*2][0], bHi + off);
                ldsm_x4(&bl[p*2][0], bLo + off);
            }
            #pragma unroll
            for (int mt = 0; mt < MT; mt++)
                #pragma unroll
                for (int nt = 0; nt < NTF; nt++) {
                    mma_bf16(acc[mt][nt], ah[mt], bh[nt]);
                    mma_bf16(acc[mt][nt], ah[mt], bl[nt]);
                    mma_bf16(acc[mt][nt], al[mt], bh[nt]);
                }
        }
    };

    fetchA(0); fetchB(0);
    storeA(0); storeB(0);
    __syncthreads();
    int buf = 0;
    for (int k0 = 0; k0 < K; k0 += 32) {
        bool has_next = (k0 + 32 < K);
        if (has_next) { fetchA(k0 + 32); fetchB(k0 + 32); }
        compute(buf);
        if (has_next) {
            storeA(buf ^ 1); storeB(buf ^ 1);
            __syncthreads();
            buf ^= 1;
        }
    }

    #pragma unroll
    for (int mt = 0; mt < MT; mt++) {
        int r = row0 + wm*(MT*16) + mt*16 + (lane >> 2);
        float bv0 = bias ? bias[r] : 0.f;
        float bv1 = bias ? bias[r+8] : 0.f;
        #pragma unroll
        for (int nt = 0; nt < NTF; nt++) {
            int n = col0 + wn*(NTF*8) + nt*8 + (lane & 3)*2;
            long i0 = (long)r*N + n;
            long i1 = (long)(r+8)*N + n;
            float2 v0 = make_float2(acc[mt][nt][0] + bv0, acc[mt][nt][1] + bv0);
            float2 v1 = make_float2(acc[mt][nt][2] + bv1, acc[mt][nt][3] + bv1);
            if (accumulate) {
                float2 o0 = *(const float2*)&Cb[i0];
                float2 o1 = *(const float2*)&Cb[i1];
                v0.x += o0.x; v0.y += o0.y; v1.x += o1.x; v1.y += o1.y;
            }
            if (Rb) {
                float2 o0 = *(const float2*)&Rb[i0];
                float2 o1 = *(const float2*)&Rb[i1];
                v0.x += o0.x; v0.y += o0.y; v1.x += o1.x; v1.y += o1.y;
            }
            *(float2*)&Cb[i0] = v0;
            *(float2*)&Cb[i1] = v1;
        }
    }
}

#define GSMB(BM,BN) (4*(BM)*80 + 4*(BN)*80)

// ---------------- merged q+k 1x1 conv: out layout (b, n, 32) each ----------------
__global__ void qk_merged(const float* __restrict__ x,
                          const float* __restrict__ Wq, const float* __restrict__ qb,
                          const float* __restrict__ Wk, const float* __restrict__ kb,
                          float* __restrict__ qout, float* __restrict__ kout, int N)
{
    __shared__ float sx[64][65];
    __shared__ float sw[64][68];
    int b = blockIdx.y, n0 = blockIdx.x * 64;
    int nl = threadIdx.x & 63, og = threadIdx.x >> 6;
    float acc[16];
    #pragma unroll
    for (int i = 0; i < 16; i++) acc[i] = 0.f;

    for (int c0 = 0; c0 < C; c0 += 64) {
        #pragma unroll
        for (int l = threadIdx.x; l < 4096; l += 256) {
            int cc = l >> 6, nn = l & 63;
            sx[cc][nn] = x[((long)b*C + c0 + cc)*N + n0 + nn];
        }
        #pragma unroll
        for (int l = threadIdx.x; l < 4096; l += 256) {
            int o = l >> 6, cc = l & 63;
            const float* wp = (o < 32) ? (Wq + o*C) : (Wk + (o - 32)*C);
            sw[o][cc] = wp[c0 + cc];
        }
        __syncthreads();
        #pragma unroll
        for (int c4 = 0; c4 < 16; c4++) {
            float x0 = sx[c4*4+0][nl], x1 = sx[c4*4+1][nl];
            float x2 = sx[c4*4+2][nl], x3 = sx[c4*4+3][nl];
            #pragma unroll
            for (int i = 0; i < 16; i++) {
                float4 w = *(const float4*)&sw[og*16 + i][c4*4];
                acc[i] += x0*w.x + x1*w.y + x2*w.z + x3*w.w;
            }
        }
        __syncthreads();
    }
    long nb = (long)(b*N + n0 + nl) * CQK;
    if (og < 2) {
        #pragma unroll
        for (int i = 0; i < 16; i++) qout[nb + og*16 + i] = acc[i] + qb[og*16 + i];
    } else {
        #pragma unroll
        for (int i = 0; i < 16; i++) kout[nb + (og-2)*16 + i] = acc[i] + kb[(og-2)*16 + i];
    }
}

// ---------------- batch softmax: softmax over b (stride NN) for each element ----------------
__global__ void batch_softmax(float* __restrict__ att, int NN)
{
    int idx = blockIdx.x * 256 + threadIdx.x;
    if (idx >= NN) return;
    float v[BATCH];
    float mx = -1e30f;
    #pragma unroll
    for (int b = 0; b < BATCH; b++) { v[b] = att[(long)b*NN + idx]; mx = fmaxf(mx, v[b]); }
    float s = 0.f;
    #pragma unroll
    for (int b = 0; b < BATCH; b++) { v[b] = fast_exp(v[b] - mx); s += v[b]; }
    float inv = 1.f / s;
    #pragma unroll
    for (int b = 0; b < BATCH; b++) att[(long)b*NN + idx] = v[b] * inv;
}

// ---------------- column softmax of gram (over c for each (b,d)), optionally accumulating ----------------
__global__ void softmax_col_add(const float* __restrict__ G, float* __restrict__ out, int accumulate)
{
    int b = blockIdx.y;
    long base = (long)b * C * C;
    int lane = threadIdx.x & 31;
    int cg = threadIdx.x >> 5;
    int d = blockIdx.x * 32 + lane;
    float vals[32];
    float mx = -1e30f;
    #pragma unroll
    for (int i = 0; i < 32; i++) {
        vals[i] = G[base + (long)(cg*32 + i)*C + d];
        mx = fmaxf(mx, vals[i]);
    }
    __shared__ float red[8][32];
    red[cg][lane] = mx;
    __syncthreads();
    if (cg == 0) {
        float m = red[0][lane];
        #pragma unroll
        for (int j = 1; j < 8; j++) m = fmaxf(m, red[j][lane]);
        red[0][lane] = m;
    }
    __syncthreads();
    mx = red[0][lane];
    __syncthreads();
    float s = 0.f;
    #pragma unroll
    for (int i = 0; i < 32; i++) { vals[i] = fast_exp(vals[i] - mx); s += vals[i]; }
    red[cg][lane] = s;
    __syncthreads();
    if (cg == 0) {
        float m = 0.f;
        #pragma unroll
        for (int j = 1; j < 8; j++) m += red[j][lane];
        red[0][lane] += m;
    }
    __syncthreads();
    float inv = 1.f / red[0][lane];
    #pragma unroll
    for (int i = 0; i < 32; i++) {
        long idx = base + (long)(cg*32 + i)*C + d;
        float v = vals[i] * inv;
        if (accumulate) v += out[idx];
        out[idx] = v;
    }
}

// ---------------- 3x3 conv, 27 output channels, halo smem, 2 rows/block ----------------
__global__ void conv3x3_off(const float* __restrict__ x, const float* __restrict__ w,
                            const float* __restrict__ bias, float* __restrict__ out,
                            int H, int Wd)
{
    int b = blockIdx.y, h0 = blockIdx.x * 2;
    int N = H * Wd;
    int tid = threadIdx.x;
    int wl = tid % Wd;
    int og = tid / Wd;
    int OCG = 256 / Wd;
    __shared__ float sx[16][4][34];
    __shared__ float sw[28][16][9];
    int ocs[4];
    #pragma unroll
    for (int g = 0; g < 4; g++) { int o = og + g*OCG; ocs[g] = (o < 27) ? o : 27; }
    float acc[2][4] = {};
    int WH = Wd + 2;
    for (int c0 = 0; c0 < C; c0 += 16) {
        for (int l = tid; l < 27*16*9; l += 256) {
            int oc = l / 144, rem = l % 144, cc = rem / 9, p = rem % 9;
            sw[oc][cc][p] = w[((long)oc*C + c0 + cc)*9 + p];
        }
        for (int l = tid; l < 16*4*WH; l += 256) {
            int cc = l / (4*WH), r = (l / WH) & 3, ww = l % WH;
            int hh = h0 + r - 1, wloc = ww - 1;
            float v = 0.f;
            if (hh >= 0 && hh < H && wloc >= 0 && wloc < Wd)
                v = x[((long)b*C + c0 + cc)*N + hh*Wd + wloc];
            sx[cc][r][ww] = v;
        }
        __syncthreads();
        for (int cc = 0; cc < 16; cc++) {
            #pragma unroll
            for (int p = 0; p < 9; p++) {
                int dy = p / 3, dx = p % 3;
                float x0 = sx[cc][dy][wl + dx];
                float x1 = sx[cc][dy + 1][wl + dx];
                #pragma unroll
                for (int g = 0; g < 4; g++) {
                    float wv = sw[ocs[g]][cc][p];
                    acc[0][g] += x0 * wv;
                    acc[1][g] += x1 * wv;
                }
            }
        }
        __syncthreads();
    }
    #pragma unroll
    for (int hr = 0; hr < 2; hr++)
        #pragma unroll
        for (int g = 0; g < 4; g++)
            if (ocs[g] < 27)
                out[((long)b*27 + ocs[g])*N + (h0 + hr)*Wd + wl] = acc[hr][g] + bias[ocs[g]];
}

// ---------------- deformable sampling -> im2col: col[b, c*9+k, hw] ----------------
__global__ void dcn_sample(const float* __restrict__ x, const float* __restrict__ off,
                           float* __restrict__ col, int H, int Wd)
{
    int b = blockIdx.z, k = blockIdx.y;
    int N = H * Wd;
    int hw0 = blockIdx.x * 64;
    __shared__ float s_w[4][64];
    __shared__ int s_a[4][64];
    int tid = threadIdx.x;
    if (tid < 64) {
        int hw = hw0 + tid;
        int h = hw / Wd, ww = hw % Wd;
        long ob = (long)b * 27 * N;
        float oy = off[ob + (2*k)*N + hw];
        float ox = off[ob + (2*k + 1)*N + hw];
        float mz = off[ob + (18 + k)*N + hw];
        float mk = 1.f / (1.f + expf(-mz));
        float y  = (float)(h - 1 + k/3) + oy;
        float xx = (float)(ww - 1 + k%3) + ox;
        float y0f = floorf(y), x0f = floorf(xx);
        float wy = y - y0f, wx = xx - x0f;
        int y0 = (int)y0f, x0 = (int)x0f;
        #pragma unroll
        for (int c2 = 0; c2 < 4; c2++) {
            int dy = c2 >> 1, dx = c2 & 1;
            int yy = y0 + dy, xc = x0 + dx;
            bool valid = (yy >= 0 && yy < H && xc >= 0 && xc < Wd);
            float wgt = (dy ? wy : 1.f - wy) * (dx ? wx : 1.f - wx) * mk;
            int yyc = min(max(yy, 0), H - 1), xcc = min(max(xc, 0), Wd - 1);
            s_w[c2][tid] = valid ? wgt : 0.f;
            s_a[c2][tid] = yyc*Wd + xcc;
        }
    }
    __syncthreads();
    int hwi = tid & 63;
    int cl = tid >> 6;
    float w0 = s_w[0][hwi], w1 = s_w[1][hwi], w2 = s_w[2][hwi], w3 = s_w[3][hwi];
    int a0 = s_a[0][hwi], a1 = s_a[1][hwi], a2 = s_a[2][hwi], a3 = s_a[3][hwi];
    for (int c = cl; c < C; c += 4) {
        const float* xp = x + ((long)b*C + c)*N;
        float v = w0*xp[a0] + w1*xp[a1] + w2*xp[a2] + w3*xp[a3];
        col[((long)b*C*9 + c*9 + k)*N + hw0 + hwi] = v;
    }
}

// ---------------- launch ----------------
extern "C" void kernel_launch(void* const* d_in, const int* in_sizes, int n_in,
                              void* d_out, int out_size)
{
    (void)in_sizes; (void)n_in; (void)out_size;
    const float* t     = (const float*)d_in[0];
    const float* s     = (const float*)d_in[1];
    const float* tq_w  = (const float*)d_in[2];
    const float* tq_b  = (const float*)d_in[3];
    const float* tk_w  = (const float*)d_in[4];
    const float* tk_b  = (const float*)d_in[5];
    const float* tv_w  = (const float*)d_in[6];
    const float* tv_b  = (const float*)d_in[7];
    const float* sq_w  = (const float*)d_in[8];
    const float* sq_b  = (const float*)d_in[9];
    const float* sk_w  = (const float*)d_in[10];
    const float* sk_b  = (const float*)d_in[11];
    const float* sv_w  = (const float*)d_in[12];
    const float* sv_b  = (const float*)d_in[13];
    const float* t_off_w = (const float*)d_in[14];
    const float* t_off_b = (const float*)d_in[15];
    const float* t_dcn_w = (const float*)d_in[16];
    const float* t_dcn_b = (const float*)d_in[17];
    const float* s_off_w = (const float*)d_in[18];
    const float* s_off_b = (const float*)d_in[19];
    const float* s_dcn_w = (const float*)d_in[20];
    const float* s_dcn_b = (const float*)d_in[21];
    float* out_t = (float*)d_out;
    float* out_s = out_t + (long)BATCH*C*NT;

    float *q_t, *k_t, *q_s, *k_s, *v_t, *v_s, *att_t, *att_s;
    float *Gt, *Gs, *Mm, *at_, *as_, *off_t, *off_s, *col_t, *col_s;
    cudaGetSymbolAddress((void**)&q_t,  g_q_t);
    cudaGetSymbolAddress((void**)&k_t,  g_k_t);
    cudaGetSymbolAddress((void**)&q_s,  g_q_s);
    cudaGetSymbolAddress((void**)&k_s,  g_k_s);
    cudaGetSymbolAddress((void**)&v_t,  g_v_t);
    cudaGetSymbolAddress((void**)&v_s,  g_v_s);
    cudaGetSymbolAddress((void**)&att_t, g_att_t);
    cudaGetSymbolAddress((void**)&att_s, g_att_s);
    cudaGetSymbolAddress((void**)&Gt,   g_Gt);
    cudaGetSymbolAddress((void**)&Gs,   g_Gs);
    cudaGetSymbolAddress((void**)&Mm,   g_M);
    cudaGetSymbolAddress((void**)&at_,  g_at);
    cudaGetSymbolAddress((void**)&as_,  g_as);
    cudaGetSymbolAddress((void**)&off_t, g_off_t);
    cudaGetSymbolAddress((void**)&off_s, g_off_s);
    cudaGetSymbolAddress((void**)&col_t, g_col_t);
    cudaGetSymbolAddress((void**)&col_s, g_col_s);

    const long CNT = (long)C*NT, CNS = (long)C*NS, CC = (long)C*C;

    cudaFuncSetAttribute(gemm_bf16x3<128,128,false>, cudaFuncAttributeMaxDynamicSharedMemorySize, GSMB(128,128));
    cudaFuncSetAttribute(gemm_bf16x3<128,64,true>,   cudaFuncAttributeMaxDynamicSharedMemorySize, GSMB(128,64));
    cudaFuncSetAttribute(gemm_bf16x3<64,64,false>,   cudaFuncAttributeMaxDynamicSharedMemorySize, GSMB(64,64));
    cudaFuncSetAttribute(gemm_bf16x3<64,64,true>,    cudaFuncAttributeMaxDynamicSharedMemorySize, GSMB(64,64));

    // 1) q,k projections (merged) and v projections
    qk_merged<<<dim3(NT/64, BATCH), 256>>>(t, tq_w, tq_b, tk_w, tk_b, q_t, k_t, NT);
    qk_merged<<<dim3(NS/64, BATCH), 256>>>(s, sq_w, sq_b, sk_w, sk_b, q_s, k_s, NS);
    gemm_bf16x3<64,64,false><<<dim3(NT/64, C/64, BATCH), 256, GSMB(64,64)>>>(tv_w, t, v_t, C, NT, C, 0, CNT, CNT, tv_b, nullptr, 0);
    gemm_bf16x3<128,128,false><<<dim3(NS/128, C/128, BATCH), 256, GSMB(128,128)>>>(sv_w, s, v_s, C, NS, C, 0, CNS, CNS, sv_b, nullptr, 0);

    // 2) spatial logits via tensor GEMM (q[b] @ k[b]^T, K=32), then batch-axis softmax
    gemm_bf16x3<64,64,true><<<dim3(NT/64, NT/64, BATCH), 256, GSMB(64,64)>>>(q_t, k_t, att_t, NT, NT, CQK, (long)NT*CQK, (long)NT*CQK, (long)NT*NT, nullptr, nullptr, 0);
    gemm_bf16x3<128,64,true><<<dim3(NS/64, NS/128, BATCH), 256, GSMB(128,64)>>>(q_s, k_s, att_s, NS, NS, CQK, (long)NS*CQK, (long)NS*CQK, (long)NS*NS, nullptr, nullptr, 0);
    batch_softmax<<<(NT*NT + 255)/256, 256>>>(att_t, NT*NT);
    batch_softmax<<<(NS*NS + 255)/256, 256>>>(att_s, NS*NS);

    // 3) spatial out = v @ att
    gemm_bf16x3<64,64,false><<<dim3(NT/64, C/64, BATCH), 256, GSMB(64,64)>>>(v_t, att_t, at_, C, NT, NT, CNT, (long)NT*NT, CNT, nullptr, nullptr, 0);
    gemm_bf16x3<128,128,false><<<dim3(NS/128, C/128, BATCH), 256, GSMB(128,128)>>>(v_s, att_s, as_, C, NS, NS, CNS, (long)NS*NS, CNS, nullptr, nullptr, 0);

    // 4) grams G = f f^T, column softmax, M = A_t + A_s
    gemm_bf16x3<64,64,true><<<dim3(C/64, C/64, BATCH), 256, GSMB(64,64)>>>(t, t, Gt, C, C, NT, CNT, CNT, CC, nullptr, nullptr, 0);
    gemm_bf16x3<64,64,true><<<dim3(C/64, C/64, BATCH), 256, GSMB(64,64)>>>(s, s, Gs, C, C, NS, CNS, CNS, CC, nullptr, nullptr, 0);
    softmax_col_add<<<dim3(C/32, BATCH), 256>>>(Gt, Mm, 0);
    softmax_col_add<<<dim3(C/32, BATCH), 256>>>(Gs, Mm, 1);

    // 5) at = (v@att) + t + M@t ; asr = (v@att) + s + M@s  (residual folded)
    gemm_bf16x3<64,64,false><<<dim3(NT/64, C/64, BATCH), 256, GSMB(64,64)>>>(Mm, t, at_, C, NT, C, CC, CNT, CNT, nullptr, t, 1);
    gemm_bf16x3<128,128,false><<<dim3(NS/128, C/128, BATCH), 256, GSMB(128,128)>>>(Mm, s, as_, C, NS, C, CC, CNS, CNS, nullptr, s, 1);

    // 6) offset/mask conv (27 channels), 2 rows per block
    conv3x3_off<<<dim3(8, BATCH), 256>>>(at_, t_off_w, t_off_b, off_t, 16, 16);
    conv3x3_off<<<dim3(16, BATCH), 256>>>(as_, s_off_w, s_off_b, off_s, 32, 32);

    // 7) deformable bilinear sampling -> im2col
    dcn_sample<<<dim3(NT/64, 9, BATCH), 256>>>(at_, off_t, col_t, 16, 16);
    dcn_sample<<<dim3(NS/64, 9, BATCH), 256>>>(as_, off_s, col_s, 32, 32);

    // 8) dcn main GEMM: out = W(256x2304) @ col + bias
    gemm_bf16x3<64,64,false><<<dim3(NT/64, C/64, BATCH), 256, GSMB(64,64)>>>(t_dcn_w, col_t, out_t, C, NT, C*9, 0, (long)C*9*NT, CNT, t_dcn_b, nullptr, 0);
    gemm_bf16x3<128,128,false><<<dim3(NS/128, C/128, BATCH), 256, GSMB(128,128)>>>(s_dcn_w, col_s, out_s, C, NS, C*9, 0, (long)C*9*NS, CNS, s_dcn_b, nullptr, 0);
}

// round 13
// speedup vs baseline: 1.0202x; 1.0202x over previous
#include <cuda_runtime.h>
#include <cuda_bf16.h>
#include <math.h>
#include <stdint.h>

#define BATCH 16
#define C 256
#define CQK 32
#define NT 256   /* 16x16 */
#define NS 1024  /* 32x32 */

// ---------------- scratch (static device memory; allowed) ----------------
__device__ float g_q_t[BATCH*NT*CQK];
__device__ float g_k_t[BATCH*NT*CQK];
__device__ float g_q_s[BATCH*NS*CQK];
__device__ float g_k_s[BATCH*NS*CQK];
__device__ float g_v_t[BATCH*C*NT];
__device__ float g_v_s[BATCH*C*NS];
__device__ float g_att_t[BATCH*NT*NT];
__device__ float g_att_s[(size_t)BATCH*NS*NS];
__device__ float g_Gt[BATCH*C*C];
__device__ float g_Gs[BATCH*C*C];
__device__ float g_M[BATCH*C*C];
__device__ float g_at[BATCH*C*NT];
__device__ float g_as[BATCH*C*NS];
__device__ float g_off_t[BATCH*27*NT];
__device__ float g_off_s[BATCH*27*NS];
__device__ float g_col_t[(size_t)BATCH*C*9*NT];
__device__ float g_col_s[(size_t)BATCH*C*9*NS];

// ---------------- helpers ----------------
__device__ __forceinline__ uint32_t cvt_pack(float lo, float hi) {
    uint32_t r;
    asm("cvt.rn.bf16x2.f32 %0, %1, %2;" : "=r"(r) : "f"(hi), "f"(lo));
    return r;
}
__device__ __forceinline__ float bfhi_lo(uint32_t p) { return __uint_as_float(p << 16); }
__device__ __forceinline__ float bfhi_hi(uint32_t p) { return __uint_as_float(p & 0xFFFF0000u); }

__device__ __forceinline__ uint32_t smem_u32(const void* p) {
    uint32_t a;
    asm("{ .reg .u64 t; cvta.to.shared.u64 t, %1; cvt.u32.u64 %0, t; }" : "=r"(a) : "l"(p));
    return a;
}

__device__ __forceinline__ void mma_bf16(float* c, const uint32_t* a, const uint32_t* b) {
    asm volatile(
        "mma.sync.aligned.m16n8k16.row.col.f32.bf16.bf16.f32 "
        "{%0,%1,%2,%3}, {%4,%5,%6,%7}, {%8,%9}, {%0,%1,%2,%3};"
        : "+f"(c[0]), "+f"(c[1]), "+f"(c[2]), "+f"(c[3])
        : "r"(a[0]), "r"(a[1]), "r"(a[2]), "r"(a[3]), "r"(b[0]), "r"(b[1]));
}

__device__ __forceinline__ void ldsm_x4(uint32_t* r, uint32_t addr) {
    asm volatile("ldmatrix.sync.aligned.m8n8.x4.shared.b16 {%0,%1,%2,%3}, [%4];"
        : "=r"(r[0]), "=r"(r[1]), "=r"(r[2]), "=r"(r[3]) : "r"(addr));
}

// MUFU-free exp: valid for x <= 0 (softmax post max-subtraction); ~2e-6 rel err.
__device__ __forceinline__ float fast_exp(float x) {
    x = fmaxf(x, -80.f);
    float t = x * 1.4426950408889634f;
    float fi = floorf(t);
    float f = t - fi;
    float p = 1.5252733804059840e-5f;
    p = p * f + 1.5403530393381609e-4f;
    p = p * f + 1.3333558146428443e-3f;
    p = p * f + 9.6181291076284772e-3f;
    p = p * f + 5.5504108664821576e-2f;
    p = p * f + 2.4022650695910071e-1f;
    p = p * f + 6.9314718055994531e-1f;
    p = p * f + 1.0f;
    int n = (int)fi;
    float scale = __int_as_float((n + 127) << 23);
    return p * scale;
}

// ---- split-bf16 tensor GEMM, ldmatrix, templated CTA tile BM x 64 x 32 ----
// BM=128: warp tile 32x32 (MT=2). BM=64: warp tile 16x32 (MT=1).
// 8 warps (4m x 2n). Smem row-major bf16 tiles, 80-byte pitch, conflict-free LDSM.
// MMA issue order groups hh / hl / lh passes: consecutive HMMAs hit different
// accumulators (dependency distance 8 instead of 1).
template<int BM, bool BT>
__global__ __launch_bounds__(256, 2)
void gemm_bf16x3(const float* __restrict__ A, const float* __restrict__ B,
                 float* __restrict__ Cc, int M_, int N, int K,
                 long sA, long sB, long sC,
                 const float* __restrict__ bias,
                 const float* __restrict__ residual, int accumulate)
{
    constexpr int MT = BM / 64;            // m16 tiles per warp
    constexpr int AI = BM / 32;            // A fetch iters
    constexpr int A_SLAB = BM * 80;        // bytes
    constexpr int B_SLAB = 5120;           // 64*80
    constexpr int B_OFF  = 4 * A_SLAB;     // bytes
    constexpr int APITCH = 20;             // u32

    extern __shared__ uint32_t sm_[];
    uint32_t sb = smem_u32(sm_);

    const float* Ab = A + (long)blockIdx.z*sA;
    const float* Bb = B + (long)blockIdx.z*sB;
    float* Cb = Cc + (long)blockIdx.z*sC;
    const float* Rb = residual ? residual + (long)blockIdx.z*sC : nullptr;

    int tid = threadIdx.x;
    int lane = tid & 31;
    int warp = tid >> 5;
    int wm = warp >> 1;                    // 0..3
    int wn = warp & 1;                     // 0..1
    int row0 = blockIdx.y * BM, col0 = blockIdx.x * 64;

    int q  = lane >> 3, qi = lane & 7;
    int a_dm = (q & 1) * 8 + qi;
    int a_dk = (q >> 1) * 16;
    int b_dn = (q >> 1) * 8 + qi;
    int b_dk = (q & 1) * 16;

    float acc[MT][4][4];
    #pragma unroll
    for (int i = 0; i < MT; i++)
        #pragma unroll
        for (int j = 0; j < 4; j++)
            #pragma unroll
            for (int r = 0; r < 4; r++) acc[i][j][r] = 0.f;

    float4 fa[AI];
    float4 fbt[BT ? 2 : 1];
    float  fbn[BT ? 1 : 2][4];

    auto fetchA = [&](int k0) {
        #pragma unroll
        for (int i = 0; i < AI; i++) {
            int slot = tid + i*256;                 // BM*8 = m x 8 k4
            int m = slot >> 3, k4 = slot & 7;
            fa[i] = *(const float4*)&Ab[(long)(row0+m)*K + k0 + k4*4];
        }
    };
    auto storeA = [&](int buf) {
        #pragma unroll
        for (int i = 0; i < AI; i++) {
            int slot = tid + i*256;
            int m = slot >> 3, k4 = slot & 7;
            float x = fa[i].x, y = fa[i].y, z = fa[i].z, w = fa[i].w;
            uint32_t h0 = cvt_pack(x, y), h1 = cvt_pack(z, w);
            uint32_t l0 = cvt_pack(x - bfhi_lo(h0), y - bfhi_hi(h0));
            uint32_t l1 = cvt_pack(z - bfhi_lo(h1), w - bfhi_hi(h1));
            int ih = ((buf*2 + 0)*BM + m)*APITCH + k4*2;
            int il = ((buf*2 + 1)*BM + m)*APITCH + k4*2;
            *(uint2*)&sm_[ih] = make_uint2(h0, h1);
            *(uint2*)&sm_[il] = make_uint2(l0, l1);
        }
    };
    auto fetchB = [&](int k0) {
        if (BT) {
            #pragma unroll
            for (int i = 0; i < 2; i++) {
                int slot = tid + i*256;             // 512 = 64n x 8 k4
                int k4 = slot & 7, n = slot >> 3;
                fbt[i] = *(const float4*)&Bb[(long)(col0+n)*K + k0 + k4*4];
            }
        } else {
            #pragma unroll
            for (int i = 0; i < 2; i++) {
                int slot = tid + i*256;             // 8 kg x 64 n
                int n = slot & 63, kg = slot >> 6;
                #pragma unroll
                for (int j = 0; j < 4; j++)
                    fbn[i][j] = Bb[(long)(k0 + kg*4 + j)*N + col0 + n];
            }
        }
    };
    auto storeB = [&](int buf) {
        #pragma unroll
        for (int i = 0; i < 2; i++) {
            int slot = tid + i*256;
            int n, k4;
            float v0, v1, v2, v3;
            if (BT) {
                n = slot >> 3; k4 = slot & 7;
                v0 = fbt[i].x; v1 = fbt[i].y; v2 = fbt[i].z; v3 = fbt[i].w;
            } else {
                n = slot & 63; k4 = slot >> 6;
                v0 = fbn[i][0]; v1 = fbn[i][1]; v2 = fbn[i][2]; v3 = fbn[i][3];
            }
            uint32_t h0 = cvt_pack(v0, v1), h1 = cvt_pack(v2, v3);
            uint32_t l0 = cvt_pack(v0 - bfhi_lo(h0), v1 - bfhi_hi(h0));
            uint32_t l1 = cvt_pack(v2 - bfhi_lo(h1), v3 - bfhi_hi(h1));
            int ih = B_OFF/4 + ((buf*2 + 0)*64 + n)*APITCH + k4*2;
            int il = B_OFF/4 + ((buf*2 + 1)*64 + n)*APITCH + k4*2;
            *(uint2*)&sm_[ih] = make_uint2(h0, h1);
            *(uint2*)&sm_[il] = make_uint2(l0, l1);
        }
    };
    auto compute = [&](int buf) {
        uint32_t aHi = sb + (buf*2 + 0)*A_SLAB;
        uint32_t aLo = sb + (buf*2 + 1)*A_SLAB;
        uint32_t bHi = sb + B_OFF + (buf*2 + 0)*B_SLAB;
        uint32_t bLo = sb + B_OFF + (buf*2 + 1)*B_SLAB;
        #pragma unroll
        for (int ks = 0; ks < 2; ks++) {
            uint32_t ah[MT][4], al[MT][4], bh[4][2], bl[4][2];
            #pragma unroll
            for (int mt = 0; mt < MT; mt++) {
                uint32_t off = (uint32_t)(wm*(MT*16) + mt*16 + a_dm)*80 + ks*32 + a_dk;
                ldsm_x4(ah[mt], aHi + off);
                ldsm_x4(al[mt], aLo + off);
            }
            #pragma unroll
            for (int p = 0; p < 2; p++) {
                uint32_t off = (uint32_t)(wn*32 + p*16 + b_dn)*80 + ks*32 + b_dk;
                ldsm_x4(&bh[p*2][0], bHi + off);
                ldsm_x4(&bl[p*2][0], bLo + off);
            }
            // grouped passes: consecutive MMAs target different accumulators
            #pragma unroll
            for (int mt = 0; mt < MT; mt++)
                #pragma unroll
                for (int nt = 0; nt < 4; nt++)
                    mma_bf16(acc[mt][nt], ah[mt], bh[nt]);
            #pragma unroll
            for (int mt = 0; mt < MT; mt++)
                #pragma unroll
                for (int nt = 0; nt < 4; nt++)
                    mma_bf16(acc[mt][nt], ah[mt], bl[nt]);
            #pragma unroll
            for (int mt = 0; mt < MT; mt++)
                #pragma unroll
                for (int nt = 0; nt < 4; nt++)
                    mma_bf16(acc[mt][nt], al[mt], bh[nt]);
        }
    };

    fetchA(0); fetchB(0);
    storeA(0); storeB(0);
    __syncthreads();
    int buf = 0;
    for (int k0 = 0; k0 < K; k0 += 32) {
        bool has_next = (k0 + 32 < K);
        if (has_next) { fetchA(k0 + 32); fetchB(k0 + 32); }
        compute(buf);
        if (has_next) {
            storeA(buf ^ 1); storeB(buf ^ 1);
            __syncthreads();
            buf ^= 1;
        }
    }

    #pragma unroll
    for (int mt = 0; mt < MT; mt++) {
        int r = row0 + wm*(MT*16) + mt*16 + (lane >> 2);
        float bv0 = bias ? bias[r] : 0.f;
        float bv1 = bias ? bias[r+8] : 0.f;
        #pragma unroll
        for (int nt = 0; nt < 4; nt++) {
            int n = col0 + wn*32 + nt*8 + (lane & 3)*2;
            long i0 = (long)r*N + n;
            long i1 = (long)(r+8)*N + n;
            float2 v0 = make_float2(acc[mt][nt][0] + bv0, acc[mt][nt][1] + bv0);
            float2 v1 = make_float2(acc[mt][nt][2] + bv1, acc[mt][nt][3] + bv1);
            if (accumulate) {
                float2 o0 = *(const float2*)&Cb[i0];
                float2 o1 = *(const float2*)&Cb[i1];
                v0.x += o0.x; v0.y += o0.y; v1.x += o1.x; v1.y += o1.y;
            }
            if (Rb) {
                float2 o0 = *(const float2*)&Rb[i0];
                float2 o1 = *(const float2*)&Rb[i1];
                v0.x += o0.x; v0.y += o0.y; v1.x += o1.x; v1.y += o1.y;
            }
            *(float2*)&Cb[i0] = v0;
            *(float2*)&Cb[i1] = v1;
        }
    }
}

#define GSMB(BM) (4*(BM)*80 + 4*5120)

// ---------------- merged q+k 1x1 conv: out layout (b, n, 32) each ----------------
__global__ void qk_merged(const float* __restrict__ x,
                          const float* __restrict__ Wq, const float* __restrict__ qb,
                          const float* __restrict__ Wk, const float* __restrict__ kb,
                          float* __restrict__ qout, float* __restrict__ kout, int N)
{
    __shared__ float sx[64][65];
    __shared__ float sw[64][68];
    int b = blockIdx.y, n0 = blockIdx.x * 64;
    int nl = threadIdx.x & 63, og = threadIdx.x >> 6;
    float acc[16];
    #pragma unroll
    for (int i = 0; i < 16; i++) acc[i] = 0.f;

    for (int c0 = 0; c0 < C; c0 += 64) {
        #pragma unroll
        for (int l = threadIdx.x; l < 4096; l += 256) {
            int cc = l >> 6, nn = l & 63;
            sx[cc][nn] = x[((long)b*C + c0 + cc)*N + n0 + nn];
        }
        #pragma unroll
        for (int l = threadIdx.x; l < 4096; l += 256) {
            int o = l >> 6, cc = l & 63;
            const float* wp = (o < 32) ? (Wq + o*C) : (Wk + (o - 32)*C);
            sw[o][cc] = wp[c0 + cc];
        }
        __syncthreads();
        #pragma unroll
        for (int c4 = 0; c4 < 16; c4++) {
            float x0 = sx[c4*4+0][nl], x1 = sx[c4*4+1][nl];
            float x2 = sx[c4*4+2][nl], x3 = sx[c4*4+3][nl];
            #pragma unroll
            for (int i = 0; i < 16; i++) {
                float4 w = *(const float4*)&sw[og*16 + i][c4*4];
                acc[i] += x0*w.x + x1*w.y + x2*w.z + x3*w.w;
            }
        }
        __syncthreads();
    }
    long nb = (long)(b*N + n0 + nl) * CQK;
    if (og < 2) {
        #pragma unroll
        for (int i = 0; i < 16; i++) qout[nb + og*16 + i] = acc[i] + qb[og*16 + i];
    } else {
        #pragma unroll
        for (int i = 0; i < 16; i++) kout[nb + (og-2)*16 + i] = acc[i] + kb[(og-2)*16 + i];
    }
}

// ---------------- batch softmax: softmax over b (stride NN) for each element ----------------
__global__ void batch_softmax(float* __restrict__ att, int NN)
{
    int idx = blockIdx.x * 256 + threadIdx.x;
    if (idx >= NN) return;
    float v[BATCH];
    float mx = -1e30f;
    #pragma unroll
    for (int b = 0; b < BATCH; b++) { v[b] = att[(long)b*NN + idx]; mx = fmaxf(mx, v[b]); }
    float s = 0.f;
    #pragma unroll
    for (int b = 0; b < BATCH; b++) { v[b] = fast_exp(v[b] - mx); s += v[b]; }
    float inv = 1.f / s;
    #pragma unroll
    for (int b = 0; b < BATCH; b++) att[(long)b*NN + idx] = v[b] * inv;
}

// ---------------- column softmax of gram (over c for each (b,d)), optionally accumulating ----------------
__global__ void softmax_col_add(const float* __restrict__ G, float* __restrict__ out, int accumulate)
{
    int b = blockIdx.y;
    long base = (long)b * C * C;
    int lane = threadIdx.x & 31;
    int cg = threadIdx.x >> 5;
    int d = blockIdx.x * 32 + lane;
    float vals[32];
    float mx = -1e30f;
    #pragma unroll
    for (int i = 0; i < 32; i++) {
        vals[i] = G[base + (long)(cg*32 + i)*C + d];
        mx = fmaxf(mx, vals[i]);
    }
    __shared__ float red[8][32];
    red[cg][lane] = mx;
    __syncthreads();
    if (cg == 0) {
        float m = red[0][lane];
        #pragma unroll
        for (int j = 1; j < 8; j++) m = fmaxf(m, red[j][lane]);
        red[0][lane] = m;
    }
    __syncthreads();
    mx = red[0][lane];
    __syncthreads();
    float s = 0.f;
    #pragma unroll
    for (int i = 0; i < 32; i++) { vals[i] = fast_exp(vals[i] - mx); s += vals[i]; }
    red[cg][lane] = s;
    __syncthreads();
    if (cg == 0) {
        float m = 0.f;
        #pragma unroll
        for (int j = 1; j < 8; j++) m += red[j][lane];
        red[0][lane] += m;
    }
    __syncthreads();
    float inv = 1.f / red[0][lane];
    #pragma unroll
    for (int i = 0; i < 32; i++) {
        long idx = base + (long)(cg*32 + i)*C + d;
        float v = vals[i] * inv;
        if (accumulate) v += out[idx];
        out[idx] = v;
    }
}

// ---------------- 3x3 conv, 27 output channels, halo smem, 2 rows/block ----------------
__global__ void conv3x3_off(const float* __restrict__ x, const float* __restrict__ w,
                            const float* __restrict__ bias, float* __restrict__ out,
                            int H, int Wd)
{
    int b = blockIdx.y, h0 = blockIdx.x * 2;
    int N = H * Wd;
    int tid = threadIdx.x;
    int wl = tid % Wd;
    int og = tid / Wd;
    int OCG = 256 / Wd;
    __shared__ float sx[16][4][34];
    __shared__ float sw[28][16][9];
    int ocs[4];
    #pragma unroll
    for (int g = 0; g < 4; g++) { int o = og + g*OCG; ocs[g] = (o < 27) ? o : 27; }
    float acc[2][4] = {};
    int WH = Wd + 2;
    for (int c0 = 0; c0 < C; c0 += 16) {
        for (int l = tid; l < 27*16*9; l += 256) {
            int oc = l / 144, rem = l % 144, cc = rem / 9, p = rem % 9;
            sw[oc][cc][p] = w[((long)oc*C + c0 + cc)*9 + p];
        }
        for (int l = tid; l < 16*4*WH; l += 256) {
            int cc = l / (4*WH), r = (l / WH) & 3, ww = l % WH;
            int hh = h0 + r - 1, wloc = ww - 1;
            float v = 0.f;
            if (hh >= 0 && hh < H && wloc >= 0 && wloc < Wd)
                v = x[((long)b*C + c0 + cc)*N + hh*Wd + wloc];
            sx[cc][r][ww] = v;
        }
        __syncthreads();
        for (int cc = 0; cc < 16; cc++) {
            #pragma unroll
            for (int p = 0; p < 9; p++) {
                int dy = p / 3, dx = p % 3;
                float x0 = sx[cc][dy][wl + dx];
                float x1 = sx[cc][dy + 1][wl + dx];
                #pragma unroll
                for (int g = 0; g < 4; g++) {
                    float wv = sw[ocs[g]][cc][p];
                    acc[0][g] += x0 * wv;
                    acc[1][g] += x1 * wv;
                }
            }
        }
        __syncthreads();
    }
    #pragma unroll
    for (int hr = 0; hr < 2; hr++)
        #pragma unroll
        for (int g = 0; g < 4; g++)
            if (ocs[g] < 27)
                out[((long)b*27 + ocs[g])*N + (h0 + hr)*Wd + wl] = acc[hr][g] + bias[ocs[g]];
}

// ---------------- deformable sampling -> im2col: col[b, c*9+k, hw] ----------------
__global__ void dcn_sample(const float* __restrict__ x, const float* __restrict__ off,
                           float* __restrict__ col, int H, int Wd)
{
    int b = blockIdx.z, k = blockIdx.y;
    int N = H * Wd;
    int hw0 = blockIdx.x * 64;
    __shared__ float s_w[4][64];
    __shared__ int s_a[4][64];
    int tid = threadIdx.x;
    if (tid < 64) {
        int hw = hw0 + tid;
        int h = hw / Wd, ww = hw % Wd;
        long ob = (long)b * 27 * N;
        float oy = off[ob + (2*k)*N + hw];
        float ox = off[ob + (2*k + 1)*N + hw];
        float mz = off[ob + (18 + k)*N + hw];
        float mk = 1.f / (1.f + expf(-mz));
        float y  = (float)(h - 1 + k/3) + oy;
        float xx = (float)(ww - 1 + k%3) + ox;
        float y0f = floorf(y), x0f = floorf(xx);
        float wy = y - y0f, wx = xx - x0f;
        int y0 = (int)y0f, x0 = (int)x0f;
        #pragma unroll
        for (int c2 = 0; c2 < 4; c2++) {
            int dy = c2 >> 1, dx = c2 & 1;
            int yy = y0 + dy, xc = x0 + dx;
            bool valid = (yy >= 0 && yy < H && xc >= 0 && xc < Wd);
            float wgt = (dy ? wy : 1.f - wy) * (dx ? wx : 1.f - wx) * mk;
            int yyc = min(max(yy, 0), H - 1), xcc = min(max(xc, 0), Wd - 1);
            s_w[c2][tid] = valid ? wgt : 0.f;
            s_a[c2][tid] = yyc*Wd + xcc;
        }
    }
    __syncthreads();
    int hwi = tid & 63;
    int cl = tid >> 6;
    float w0 = s_w[0][hwi], w1 = s_w[1][hwi], w2 = s_w[2][hwi], w3 = s_w[3][hwi];
    int a0 = s_a[0][hwi], a1 = s_a[1][hwi], a2 = s_a[2][hwi], a3 = s_a[3][hwi];
    for (int c = cl; c < C; c += 4) {
        const float* xp = x + ((long)b*C + c)*N;
        float v = w0*xp[a0] + w1*xp[a1] + w2*xp[a2] + w3*xp[a3];
        col[((long)b*C*9 + c*9 + k)*N + hw0 + hwi] = v;
    }
}

// ---------------- launch ----------------
extern "C" void kernel_launch(void* const* d_in, const int* in_sizes, int n_in,
                              void* d_out, int out_size)
{
    (void)in_sizes; (void)n_in; (void)out_size;
    const float* t     = (const float*)d_in[0];
    const float* s     = (const float*)d_in[1];
    const float* tq_w  = (const float*)d_in[2];
    const float* tq_b  = (const float*)d_in[3];
    const float* tk_w  = (const float*)d_in[4];
    const float* tk_b  = (const float*)d_in[5];
    const float* tv_w  = (const float*)d_in[6];
    const float* tv_b  = (const float*)d_in[7];
    const float* sq_w  = (const float*)d_in[8];
    const float* sq_b  = (const float*)d_in[9];
    const float* sk_w  = (const float*)d_in[10];
    const float* sk_b  = (const float*)d_in[11];
    const float* sv_w  = (const float*)d_in[12];
    const float* sv_b  = (const float*)d_in[13];
    const float* t_off_w = (const float*)d_in[14];
    const float* t_off_b = (const float*)d_in[15];
    const float* t_dcn_w = (const float*)d_in[16];
    const float* t_dcn_b = (const float*)d_in[17];
    const float* s_off_w = (const float*)d_in[18];
    const float* s_off_b = (const float*)d_in[19];
    const float* s_dcn_w = (const float*)d_in[20];
    const float* s_dcn_b = (const float*)d_in[21];
    float* out_t = (float*)d_out;
    float* out_s = out_t + (long)BATCH*C*NT;

    float *q_t, *k_t, *q_s, *k_s, *v_t, *v_s, *att_t, *att_s;
    float *Gt, *Gs, *Mm, *at_, *as_, *off_t, *off_s, *col_t, *col_s;
    cudaGetSymbolAddress((void**)&q_t,  g_q_t);
    cudaGetSymbolAddress((void**)&k_t,  g_k_t);
    cudaGetSymbolAddress((void**)&q_s,  g_q_s);
    cudaGetSymbolAddress((void**)&k_s,  g_k_s);
    cudaGetSymbolAddress((void**)&v_t,  g_v_t);
    cudaGetSymbolAddress((void**)&v_s,  g_v_s);
    cudaGetSymbolAddress((void**)&att_t, g_att_t);
    cudaGetSymbolAddress((void**)&att_s, g_att_s);
    cudaGetSymbolAddress((void**)&Gt,   g_Gt);
    cudaGetSymbolAddress((void**)&Gs,   g_Gs);
    cudaGetSymbolAddress((void**)&Mm,   g_M);
    cudaGetSymbolAddress((void**)&at_,  g_at);
    cudaGetSymbolAddress((void**)&as_,  g_as);
    cudaGetSymbolAddress((void**)&off_t, g_off_t);
    cudaGetSymbolAddress((void**)&off_s, g_off_s);
    cudaGetSymbolAddress((void**)&col_t, g_col_t);
    cudaGetSymbolAddress((void**)&col_s, g_col_s);

    const long CNT = (long)C*NT, CNS = (long)C*NS, CC = (long)C*C;

    cudaFuncSetAttribute(gemm_bf16x3<128,false>, cudaFuncAttributeMaxDynamicSharedMemorySize, GSMB(128));
    cudaFuncSetAttribute(gemm_bf16x3<128,true>,  cudaFuncAttributeMaxDynamicSharedMemorySize, GSMB(128));
    cudaFuncSetAttribute(gemm_bf16x3<64,false>,  cudaFuncAttributeMaxDynamicSharedMemorySize, GSMB(64));
    cudaFuncSetAttribute(gemm_bf16x3<64,true>,   cudaFuncAttributeMaxDynamicSharedMemorySize, GSMB(64));

    // 1) q,k projections (merged) and v projections
    qk_merged<<<dim3(NT/64, BATCH), 256>>>(t, tq_w, tq_b, tk_w, tk_b, q_t, k_t, NT);
    qk_merged<<<dim3(NS/64, BATCH), 256>>>(s, sq_w, sq_b, sk_w, sk_b, q_s, k_s, NS);
    gemm_bf16x3<64,false><<<dim3(NT/64, C/64, BATCH), 256, GSMB(64)>>>(tv_w, t, v_t, C, NT, C, 0, CNT, CNT, tv_b, nullptr, 0);
    gemm_bf16x3<128,false><<<dim3(NS/64, C/128, BATCH), 256, GSMB(128)>>>(sv_w, s, v_s, C, NS, C, 0, CNS, CNS, sv_b, nullptr, 0);

    // 2) spatial logits via tensor GEMM (q[b] @ k[b]^T, K=32), then batch-axis softmax
    gemm_bf16x3<64,true><<<dim3(NT/64, NT/64, BATCH), 256, GSMB(64)>>>(q_t, k_t, att_t, NT, NT, CQK, (long)NT*CQK, (long)NT*CQK, (long)NT*NT, nullptr, nullptr, 0);
    gemm_bf16x3<128,true><<<dim3(NS/64, NS/128, BATCH), 256, GSMB(128)>>>(q_s, k_s, att_s, NS, NS, CQK, (long)NS*CQK, (long)NS*CQK, (long)NS*NS, nullptr, nullptr, 0);
    batch_softmax<<<(NT*NT + 255)/256, 256>>>(att_t, NT*NT);
    batch_softmax<<<(NS*NS + 255)/256, 256>>>(att_s, NS*NS);

    // 3) spatial out = v @ att
    gemm_bf16x3<64,false><<<dim3(NT/64, C/64, BATCH), 256, GSMB(64)>>>(v_t, att_t, at_, C, NT, NT, CNT, (long)NT*NT, CNT, nullptr, nullptr, 0);
    gemm_bf16x3<128,false><<<dim3(NS/64, C/128, BATCH), 256, GSMB(128)>>>(v_s, att_s, as_, C, NS, NS, CNS, (long)NS*NS, CNS, nullptr, nullptr, 0);

    // 4) grams G = f f^T (split-bf16 tensor, BM=64 for occupancy), column softmax, M = A_t + A_s
    gemm_bf16x3<64,true><<<dim3(C/64, C/64, BATCH), 256, GSMB(64)>>>(t, t, Gt, C, C, NT, CNT, CNT, CC, nullptr, nullptr, 0);
    gemm_bf16x3<64,true><<<dim3(C/64, C/64, BATCH), 256, GSMB(64)>>>(s, s, Gs, C, C, NS, CNS, CNS, CC, nullptr, nullptr, 0);
    softmax_col_add<<<dim3(C/32, BATCH), 256>>>(Gt, Mm, 0);
    softmax_col_add<<<dim3(C/32, BATCH), 256>>>(Gs, Mm, 1);

    // 5) at = (v@att) + t + M@t ; asr = (v@att) + s + M@s  (residual folded)
    gemm_bf16x3<64,false><<<dim3(NT/64, C/64, BATCH), 256, GSMB(64)>>>(Mm, t, at_, C, NT, C, CC, CNT, CNT, nullptr, t, 1);
    gemm_bf16x3<128,false><<<dim3(NS/64, C/128, BATCH), 256, GSMB(128)>>>(Mm, s, as_, C, NS, C, CC, CNS, CNS, nullptr, s, 1);

    // 6) offset/mask conv (27 channels), 2 rows per block
    conv3x3_off<<<dim3(8, BATCH), 256>>>(at_, t_off_w, t_off_b, off_t, 16, 16);
    conv3x3_off<<<dim3(16, BATCH), 256>>>(as_, s_off_w, s_off_b, off_s, 32, 32);

    // 7) deformable bilinear sampling -> im2col
    dcn_sample<<<dim3(NT/64, 9, BATCH), 256>>>(at_, off_t, col_t, 16, 16);
    dcn_sample<<<dim3(NS/64, 9, BATCH), 256>>>(as_, off_s, col_s, 32, 32);

    // 8) dcn main GEMM: out = W(256x2304) @ col + bias
    gemm_bf16x3<64,false><<<dim3(NT/64, C/64, BATCH), 256, GSMB(64)>>>(t_dcn_w, col_t, out_t, C, NT, C*9, 0, (long)C*9*NT, CNT, t_dcn_b, nullptr, 0);
    gemm_bf16x3<128,false><<<dim3(NS/64, C/128, BATCH), 256, GSMB(128)>>>(s_dcn_w, col_s, out_s, C, NS, C*9, 0, (long)C*9*NS, CNS, s_dcn_b, nullptr, 0);
}